// round 14
// baseline (speedup 1.0000x reference)
#include <cuda_runtime.h>
#include <cuda_fp16.h>

#define NMAX 50000
#define EMAX 800000
#define CLUS 256
#define FOU1 128
#define FOU2 256
#define HLIN 256
#define OUTP 10
#define KSPLIT3 111   // k-split for k3 (4 * 111 = 444 blocks = 3 CTA/SM)

// ---------------- static scratch ----------------
__device__ __align__(32) float d_agg[NMAX * 8];         // [0..4]=sum x[src], [5]=cnt
__device__ __align__(32) float d_x8[NMAX * 8];          // padded copy of x
__device__ float  d_deg[NMAX];                          // weighted out-degree (src)
__device__ __half d_S16[(size_t)NMAX * CLUS];           // softmax S, fp16 (GEMM)
__device__ char   d_Q8[(size_t)NMAX * CLUS];            // int8 of (S-1/256)*srow
__device__ float2 d_aux[NMAX];                          // {rsqrt(deg) or 0, row inv-scale}
__device__ __half d_Y16[(size_t)NMAX * FOU1];           // relu features, fp16
__device__ float  d_pooled[CLUS * FOU1];                // atomically accumulated
__device__ float  d_ysum[FOU1];                         // sum_i Y[i]
__device__ float  d_g[FOU2];                            // sum_c y2[c]
__device__ float  d_scal[3];                            // [0]=diag, [1]=edge residual, [2]=sum c_e

// ---------------- K0: zero accumulators + pad x ----------------
__global__ void k0_zero(const float* __restrict__ x, int n) {
    int tot = n * 8 + n * 8 + n + CLUS * FOU1 + FOU1 + FOU2 + 3;
    for (int i = blockIdx.x * blockDim.x + threadIdx.x; i < tot;
         i += gridDim.x * blockDim.x) {
        int j = i;
        if (j < n * 8)       { d_agg[j] = 0.f; continue; } j -= n * 8;
        if (j < n * 8)       { int k = j & 7;
                               d_x8[j] = (k < 5) ? x[(j >> 3) * 5 + k] : 0.f; continue; } j -= n * 8;
        if (j < n)           { d_deg[j]    = 0.f; continue; } j -= n;
        if (j < CLUS * FOU1) { d_pooled[j] = 0.f; continue; } j -= CLUS * FOU1;
        if (j < FOU1)        { d_ysum[j]   = 0.f; continue; } j -= FOU1;
        if (j < FOU2)        { d_g[j]      = 0.f; continue; } j -= FOU2;
        d_scal[j] = 0.f;
    }
}

// ---------------- K1: edge aggregation (vector gather + vector red) ----------------
__global__ void k1_edge_agg(const int* __restrict__ ei, const float* __restrict__ w,
                            int n, int e) {
    for (int j = blockIdx.x * blockDim.x + threadIdx.x; j < e;
         j += gridDim.x * blockDim.x) {
        int s = ei[j];
        int d = ei[e + j];
        float wv = w[j];
        float4 v0 = *(const float4*)&d_x8[(size_t)s * 8];
        float  v4 = d_x8[(size_t)s * 8 + 4];
        float* base = &d_agg[(size_t)d * 8];
        float one = 1.0f;
        asm volatile("red.global.add.v4.f32 [%0], {%1,%2,%3,%4};"
                     :: "l"(base), "f"(v0.x), "f"(v0.y), "f"(v0.z), "f"(v0.w) : "memory");
        asm volatile("red.global.add.v2.f32 [%0], {%1,%2};"
                     :: "l"(base + 4), "f"(v4), "f"(one) : "memory");
        atomicAdd(&d_deg[s], wv);
    }
}

// ---------------- K2: conv -> softmax S (fp16 + int8 residual) / relu Y  (R4 form) ----------------
__global__ __launch_bounds__(256) void k2_node(
    const float* __restrict__ x,
    const float* __restrict__ W1p, const float* __restrict__ R1p, const float* __restrict__ b1p,
    const float* __restrict__ W1e, const float* __restrict__ R1e, const float* __restrict__ b1e,
    int n) {
    __shared__ float ysh[FOU1];
    __shared__ float red[8];
    for (int t = threadIdx.x; t < FOU1; t += blockDim.x) ysh[t] = 0.f;
    __syncthreads();

    int lane = threadIdx.x & 31;
    int wid  = threadIdx.x >> 5;
    int warpsTotal = gridDim.x * 8;
    int gw = blockIdx.x * 8 + wid;

    float yloc[4] = {0.f, 0.f, 0.f, 0.f};
    float dacc = 0.f;

    for (int i = gw; i < n; i += warpsTotal) {
        float xv = 0.f, av = 0.f;
        if (lane < 5) { xv = x[i * 5 + lane]; }
        if (lane < 6) { av = d_agg[(size_t)i * 8 + lane]; }
        float cv   = __shfl_sync(0xffffffffu, av, 5);
        float degv = d_deg[i];
        float denom = fmaxf(cv, 1.0f);
        float xa[5], aa[5];
#pragma unroll
        for (int k = 0; k < 5; k++) {
            xa[k] = __shfl_sync(0xffffffffu, xv, k);
            aa[k] = __shfl_sync(0xffffffffu, av, k) / denom;
        }
        float sv[8];
#pragma unroll
        for (int j = 0; j < 8; j++) {
            int c = j * 32 + lane;
            float acc = b1p[c];
#pragma unroll
            for (int k = 0; k < 5; k++) {
                acc = fmaf(aa[k], W1p[k * 256 + c], acc);
                acc = fmaf(xa[k], R1p[k * 256 + c], acc);
            }
            sv[j] = acc;
        }
        float m = sv[0];
#pragma unroll
        for (int j = 1; j < 8; j++) m = fmaxf(m, sv[j]);
#pragma unroll
        for (int o = 16; o > 0; o >>= 1) m = fmaxf(m, __shfl_xor_sync(0xffffffffu, m, o));
        float sum = 0.f;
#pragma unroll
        for (int j = 0; j < 8; j++) { sv[j] = __expf(sv[j] - m); sum += sv[j]; }
#pragma unroll
        for (int o = 16; o > 0; o >>= 1) sum += __shfl_xor_sync(0xffffffffu, sum, o);
        float inv = 1.0f / sum;
        float sq = 0.f;
        float maxr = 0.f;
#pragma unroll
        for (int j = 0; j < 8; j++) {
            float p = sv[j] * inv;
            sv[j] = p;
            d_S16[(size_t)i * 256 + j * 32 + lane] = __float2half_rn(p);
            maxr = fmaxf(maxr, fabsf(p - 0.00390625f));
            sq = fmaf(p, p, sq);
        }
#pragma unroll
        for (int o = 16; o > 0; o >>= 1) maxr = fmaxf(maxr, __shfl_xor_sync(0xffffffffu, maxr, o));
        float srow   = (maxr > 0.f) ? 127.0f / maxr : 0.f;
        float invrow = maxr * (1.0f / 127.0f);
#pragma unroll
        for (int j = 0; j < 8; j++) {
            int q = __float2int_rn((sv[j] - 0.00390625f) * srow);
            d_Q8[(size_t)i * 256 + j * 32 + lane] = (char)q;
        }
        if (lane == 0) {
            float isq = (degv > 0.f) ? rsqrtf(degv) : 0.f;
            d_aux[i] = make_float2(isq, invrow);
        }
        if (degv > 0.f) dacc += sq;
#pragma unroll
        for (int j = 0; j < 4; j++) {
            int c = j * 32 + lane;
            float acc = b1e[c];
#pragma unroll
            for (int k = 0; k < 5; k++) {
                acc = fmaf(aa[k], W1e[k * 128 + c], acc);
                acc = fmaf(xa[k], R1e[k * 128 + c], acc);
            }
            acc = fmaxf(acc, 0.f);
            d_Y16[(size_t)i * 128 + c] = __float2half_rn(acc);
            yloc[j] += acc;
        }
    }
#pragma unroll
    for (int o = 16; o > 0; o >>= 1) dacc += __shfl_xor_sync(0xffffffffu, dacc, o);
    if (lane == 0) red[wid] = dacc;
#pragma unroll
    for (int j = 0; j < 4; j++) atomicAdd(&ysh[j * 32 + lane], yloc[j]);
    __syncthreads();
    if (threadIdx.x == 0) {
        float t = 0.f;
        for (int k = 0; k < 8; k++) t += red[k];
        atomicAdd(&d_scal[0], t);
    }
    if (threadIdx.x < FOU1) atomicAdd(&d_ysum[threadIdx.x], ysh[threadIdx.x]);
}

// ---------------- K3: pooled += S^T Y, 128c x 64f tiles, 3 CTA/SM, cp.async ----------------
#define CHUNK 32
#define APITCH 136
#define BPITCH 72

__device__ __forceinline__ unsigned shaddr(const void* p) {
    return (unsigned)__cvta_generic_to_shared(p);
}
__device__ __forceinline__ void ldsm4t(unsigned* r, unsigned addr) {
    asm volatile("ldmatrix.sync.aligned.m8n8.x4.trans.shared.b16 {%0,%1,%2,%3}, [%4];"
                 : "=r"(r[0]), "=r"(r[1]), "=r"(r[2]), "=r"(r[3]) : "r"(addr));
}
__device__ __forceinline__ void mma16816(float* c, const unsigned* a, const unsigned* b) {
    asm volatile("mma.sync.aligned.m16n8k16.row.col.f32.f16.f16.f32 "
                 "{%0,%1,%2,%3}, {%4,%5,%6,%7}, {%8,%9}, {%0,%1,%2,%3};"
                 : "+f"(c[0]), "+f"(c[1]), "+f"(c[2]), "+f"(c[3])
                 : "r"(a[0]), "r"(a[1]), "r"(a[2]), "r"(a[3]), "r"(b[0]), "r"(b[1]));
}
__device__ __forceinline__ void cpasync4(unsigned saddr, const void* g, int sz) {
    asm volatile("cp.async.ca.shared.global [%0], [%1], 4, %2;"
                 :: "r"(saddr), "l"(g), "r"(sz) : "memory");
}

__global__ __launch_bounds__(256, 3) void k3_pool(int n) {
    __shared__ __align__(16) __half A_s[2][CHUNK][APITCH];   // S chunk, 128 chalf cols
    __shared__ __align__(16) __half B_s[2][CHUNK][BPITCH];   // Y chunk, 64 fhalf cols
    int b     = blockIdx.x;
    int chalf = b & 1;
    int fhalf = (b >> 1) & 1;
    int kb    = b >> 2;
    int per   = (n + KSPLIT3 - 1) / KSPLIT3;
    int lo    = kb * per;
    int hi    = min(n, lo + per);

    int tid  = threadIdx.x;
    int lane = tid & 31;
    int wid  = tid >> 5;
    int m_base  = (wid >> 1) * 32;    // 4 m-tiles of 32 within 128
    int f_basew = (wid & 1) * 32;     // 2 f-tiles of 32 within 64

    float acc[2][4][4];
#pragma unroll
    for (int p = 0; p < 2; p++)
#pragma unroll
        for (int q = 0; q < 4; q++)
#pragma unroll
            for (int v = 0; v < 4; v++) acc[p][q][v] = 0.f;

    auto issue = [&](int i0, int bf) {
        // A: 32 rows x 64 half2
#pragma unroll
        for (int rep = 0; rep < 8; rep++) {
            int e2    = rep * 256 + tid;
            int i_loc = e2 >> 6;
            int c2    = e2 & 63;
            int g     = i0 + i_loc;
            int gc    = min(g, n - 1);
            int sz    = (g < hi) ? 4 : 0;
            cpasync4(shaddr(&A_s[bf][i_loc][2 * c2]),
                     &d_S16[(size_t)gc * 256 + chalf * 128 + 2 * c2], sz);
        }
        // B: 32 rows x 32 half2
#pragma unroll
        for (int rep = 0; rep < 4; rep++) {
            int e2    = rep * 256 + tid;
            int i_loc = e2 >> 5;
            int c2    = e2 & 31;
            int g     = i0 + i_loc;
            int gc    = min(g, n - 1);
            int sz    = (g < hi) ? 4 : 0;
            cpasync4(shaddr(&B_s[bf][i_loc][2 * c2]),
                     &d_Y16[(size_t)gc * 128 + fhalf * 64 + 2 * c2], sz);
        }
    };

    int buf = 0;
    if (lo < hi) {
        issue(lo, 0);
        asm volatile("cp.async.commit_group;" ::: "memory");
    }
    for (int i0 = lo; i0 < hi; i0 += CHUNK) {
        int nxt = i0 + CHUNK;
        if (nxt < hi) {
            issue(nxt, buf ^ 1);
            asm volatile("cp.async.commit_group;" ::: "memory");
            asm volatile("cp.async.wait_group 1;" ::: "memory");
        } else {
            asm volatile("cp.async.wait_group 0;" ::: "memory");
        }
        __syncthreads();
#pragma unroll
        for (int t = 0; t < 2; t++) {
            int krA = t * 16 + (lane & 7) + ((lane >> 4) << 3);
            unsigned aaddr = shaddr(&A_s[buf][krA][m_base + ((lane >> 3) & 1) * 8]);
            unsigned afrag[2][4];
            ldsm4t(afrag[0], aaddr);
            ldsm4t(afrag[1], aaddr + 32);
            int krB = t * 16 + (lane & 7) + (lane & 8);
            unsigned baddr = shaddr(&B_s[buf][krB][f_basew + ((lane >> 4) & 1) * 8]);
            unsigned bfrag[2][4];
#pragma unroll
            for (int gq = 0; gq < 2; gq++)
                ldsm4t(bfrag[gq], baddr + gq * 32);
#pragma unroll
            for (int p = 0; p < 2; p++)
#pragma unroll
                for (int q = 0; q < 4; q++)
                    mma16816(acc[p][q], afrag[p], &bfrag[q >> 1][(q & 1) * 2]);
        }
        __syncthreads();
        buf ^= 1;
    }

    int r    = lane >> 2;
    int col2 = (lane & 3) * 2;
#pragma unroll
    for (int p = 0; p < 2; p++) {
#pragma unroll
        for (int q = 0; q < 4; q++) {
            int cg = chalf * 128 + m_base + p * 16 + r;
            int f  = fhalf * 64 + f_basew + q * 8 + col2;
            float* p0 = &d_pooled[(size_t)cg * FOU1 + f];
            float* p1 = &d_pooled[(size_t)(cg + 8) * FOU1 + f];
            asm volatile("red.global.add.v2.f32 [%0], {%1,%2};"
                         :: "l"(p0), "f"(acc[p][q][0]), "f"(acc[p][q][1]) : "memory");
            asm volatile("red.global.add.v2.f32 [%0], {%1,%2};"
                         :: "l"(p1), "f"(acc[p][q][2]), "f"(acc[p][q][3]) : "memory");
        }
    }
}

// ---------------- K5: edge SDDMM, 4 edges/warp (8 lanes each), int8 DP4A ----------------
__global__ __launch_bounds__(256) void k5_edge(const int* __restrict__ ei,
                                               const float* __restrict__ w, int e) {
    __shared__ float redr[8];
    __shared__ float redc[8];
    int lane = threadIdx.x & 31;
    int sub  = lane & 7;      // 8 lanes per edge, each reads 32B of the 256B row
    int quar = lane >> 3;     // which of 4 edges in this warp
    int wid  = threadIdx.x >> 5;
    int gw = blockIdx.x * 8 + wid;
    int tw = gridDim.x * 8;
    float accr = 0.f;   // sum c_e * <r_i, r_j>  (scales folded in)
    float accc = 0.f;   // 8 * sum c_e
#pragma unroll 2
    for (int j = 4 * gw + quar; j < e; j += 4 * tw) {
        int s = ei[j];
        int d = ei[e + j];
        float wv = w[j];
        float2 as = d_aux[s];
        float2 ad = d_aux[d];
        float csc = wv * as.x * ad.x;
        float scl = csc * as.y * ad.y;
        const int4* ps = (const int4*)&d_Q8[(size_t)s * 256];
        const int4* pd = (const int4*)&d_Q8[(size_t)d * 256];
        int4 a0 = ps[2 * sub];
        int4 a1 = ps[2 * sub + 1];
        int4 b0 = pd[2 * sub];
        int4 b1 = pd[2 * sub + 1];
        int id = __dp4a(a0.x, b0.x, __dp4a(a0.y, b0.y,
                 __dp4a(a0.z, b0.z, __dp4a(a0.w, b0.w, 0))));
        id     = __dp4a(a1.x, b1.x, __dp4a(a1.y, b1.y,
                 __dp4a(a1.z, b1.z, __dp4a(a1.w, b1.w, id))));
        accr = fmaf(scl, (float)id, accr);
        accc += csc;
    }
#pragma unroll
    for (int o = 16; o > 0; o >>= 1) {
        accr += __shfl_xor_sync(0xffffffffu, accr, o);
        accc += __shfl_xor_sync(0xffffffffu, accc, o);
    }
    if (lane == 0) { redr[wid] = accr; redc[wid] = accc * (1.0f / 8.0f); }
    __syncthreads();
    if (threadIdx.x == 0) {
        float tr = 0.f, tc = 0.f;
        for (int k = 0; k < 8; k++) { tr += redr[k]; tc += redc[k]; }
        atomicAdd(&d_scal[1], tr);
        atomicAdd(&d_scal[2], tc);
    }
}

// ---------------- K6: g[k] += relu(mw[k] + pooled[c] . R2e[:,k]) ----------------
__global__ __launch_bounds__(256) void k6_y2(const float* __restrict__ R2e,
                                             const float* __restrict__ W2e,
                                             const float* __restrict__ b2e) {
    __shared__ float prow[FOU1];
    __shared__ float ys[FOU1];
    int c = blockIdx.x;
    if (threadIdx.x < FOU1) {
        prow[threadIdx.x] = d_pooled[c * FOU1 + threadIdx.x];
        ys[threadIdx.x]   = d_ysum[threadIdx.x] * (1.0f / 256.0f);
    }
    __syncthreads();
    int k = threadIdx.x;
    float acc = b2e[k];
#pragma unroll 4
    for (int f = 0; f < FOU1; f++) {
        acc = fmaf(ys[f],   W2e[f * 256 + k], acc);
        acc = fmaf(prow[f], R2e[f * 256 + k], acc);
    }
    acc = fmaxf(acc, 0.f);
    atomicAdd(&d_g[k], acc);
}

// ---------------- K7: MLP head + log_softmax + reg1 ----------------
__global__ __launch_bounds__(256) void k7_final(
    const float* __restrict__ Wl1, const float* __restrict__ bl1,
    const float* __restrict__ Wl2, const float* __restrict__ bl2,
    float* __restrict__ out, int n, int out_size) {
    __shared__ float gsh[FOU2];
    __shared__ float h1[HLIN];
    __shared__ float lg[OUTP];
    int t = threadIdx.x;
    gsh[t] = d_g[t];
    __syncthreads();
    float acc = bl1[t];
    for (int k = 0; k < FOU2; k++) acc = fmaf(gsh[k], Wl1[k * HLIN + t], acc);
    h1[t] = fmaxf(acc, 0.f);
    __syncthreads();
    if (t < OUTP) {
        float a2 = bl2[t];
        for (int j = 0; j < HLIN; j++) a2 = fmaf(h1[j], Wl2[j * OUTP + t], a2);
        lg[t] = a2;
    }
    __syncthreads();
    if (t == 0) {
        float m = lg[0];
        for (int o = 1; o < OUTP; o++) m = fmaxf(m, lg[o]);
        float s = 0.f;
        for (int o = 0; o < OUTP; o++) s += expf(lg[o] - m);
        float lse = m + logf(s);
        for (int o = 0; o < OUTP; o++) out[o] = lg[o] - lse;
        if (out_size > OUTP) {
            float edge = d_scal[2] * 0.00390625f + d_scal[1];
            out[OUTP] = (d_scal[0] - edge) / (float)n;
        }
    }
}

// ---------------- launch ----------------
extern "C" void kernel_launch(void* const* d_in, const int* in_sizes, int n_in,
                              void* d_out, int out_size) {
    const float* x   = (const float*)d_in[0];
    const int*   ei  = (const int*)d_in[1];
    const float* wht = (const float*)d_in[2];
    const float* W1p = (const float*)d_in[3];
    const float* R1p = (const float*)d_in[4];
    const float* b1p = (const float*)d_in[5];
    const float* W1e = (const float*)d_in[6];
    const float* R1e = (const float*)d_in[7];
    const float* b1e = (const float*)d_in[8];
    // d_in[9..11] = W2p, R2p, b2p: dead (softmax over size-1 axis == 1)
    const float* W2e = (const float*)d_in[12];
    const float* R2e = (const float*)d_in[13];
    const float* b2e = (const float*)d_in[14];
    const float* Wl1 = (const float*)d_in[15];
    const float* bl1 = (const float*)d_in[16];
    const float* Wl2 = (const float*)d_in[17];
    const float* bl2 = (const float*)d_in[18];

    int n = in_sizes[0] / 5;
    int e = in_sizes[2];

    k0_zero<<<512, 256>>>(x, n);
    k1_edge_agg<<<(e + 255) / 256, 256>>>(ei, wht, n, e);
    k2_node<<<592, 256>>>(x, W1p, R1p, b1p, W1e, R1e, b1e, n);
    k5_edge<<<1184, 256>>>(ei, wht, e);      // slot 4: ncu profiles this launch
    k3_pool<<<4 * KSPLIT3, 256>>>(n);
    k6_y2<<<CLUS, 256>>>(R2e, W2e, b2e);
    k7_final<<<1, 256>>>(Wl1, bl1, Wl2, bl2, (float*)d_out, n, out_size);
}

// round 15
// speedup vs baseline: 1.0583x; 1.0583x over previous
#include <cuda_runtime.h>
#include <cuda_fp16.h>

#define NMAX 50000
#define EMAX 800000
#define CLUS 256
#define FOU1 128
#define FOU2 256
#define HLIN 256
#define OUTP 10
#define KSPLIT3 111   // k-split for k3 (4 * 111 = 444 blocks = 3 CTA/SM)

// ---------------- static scratch ----------------
__device__ __align__(32) float d_agg[NMAX * 8];         // [0..4]=sum x[src], [5]=cnt
__device__ __align__(32) float d_x8[NMAX * 8];          // padded copy of x
__device__ float  d_deg[NMAX];                          // weighted out-degree (src)
__device__ __half d_S16[(size_t)NMAX * CLUS];           // softmax S, fp16 (GEMM)
__device__ char   d_Q8[(size_t)NMAX * CLUS];            // int8 of (S-1/256)*srow
__device__ float2 d_aux[NMAX];                          // {rsqrt(deg) or 0, row inv-scale}
__device__ __half d_Y16[(size_t)NMAX * FOU1];           // relu features, fp16
__device__ float  d_pooled[CLUS * FOU1];                // atomically accumulated
__device__ float  d_ysum[FOU1];                         // sum_i Y[i]
__device__ float  d_g[FOU2];                            // sum_c y2[c]
__device__ float  d_scal[3];                            // [0]=diag, [1]=edge residual, [2]=sum c_e

// ---------------- K0: zero accumulators + pad x ----------------
__global__ void k0_zero(const float* __restrict__ x, int n) {
    int tot = n * 8 + n * 8 + n + CLUS * FOU1 + FOU1 + FOU2 + 3;
    for (int i = blockIdx.x * blockDim.x + threadIdx.x; i < tot;
         i += gridDim.x * blockDim.x) {
        int j = i;
        if (j < n * 8)       { d_agg[j] = 0.f; continue; } j -= n * 8;
        if (j < n * 8)       { int k = j & 7;
                               d_x8[j] = (k < 5) ? x[(j >> 3) * 5 + k] : 0.f; continue; } j -= n * 8;
        if (j < n)           { d_deg[j]    = 0.f; continue; } j -= n;
        if (j < CLUS * FOU1) { d_pooled[j] = 0.f; continue; } j -= CLUS * FOU1;
        if (j < FOU1)        { d_ysum[j]   = 0.f; continue; } j -= FOU1;
        if (j < FOU2)        { d_g[j]      = 0.f; continue; } j -= FOU2;
        d_scal[j] = 0.f;
    }
}

// ---------------- K1: edge aggregation (vector gather + vector red) ----------------
__global__ void k1_edge_agg(const int* __restrict__ ei, const float* __restrict__ w,
                            int n, int e) {
    for (int j = blockIdx.x * blockDim.x + threadIdx.x; j < e;
         j += gridDim.x * blockDim.x) {
        int s = ei[j];
        int d = ei[e + j];
        float wv = w[j];
        float4 v0 = *(const float4*)&d_x8[(size_t)s * 8];
        float  v4 = d_x8[(size_t)s * 8 + 4];
        float* base = &d_agg[(size_t)d * 8];
        float one = 1.0f;
        asm volatile("red.global.add.v4.f32 [%0], {%1,%2,%3,%4};"
                     :: "l"(base), "f"(v0.x), "f"(v0.y), "f"(v0.z), "f"(v0.w) : "memory");
        asm volatile("red.global.add.v2.f32 [%0], {%1,%2};"
                     :: "l"(base + 4), "f"(v4), "f"(one) : "memory");
        atomicAdd(&d_deg[s], wv);
    }
}

// ---------------- K2: conv -> softmax S (fp16 + int8 residual) / relu Y  (R4 form) ----------------
__global__ __launch_bounds__(256) void k2_node(
    const float* __restrict__ x,
    const float* __restrict__ W1p, const float* __restrict__ R1p, const float* __restrict__ b1p,
    const float* __restrict__ W1e, const float* __restrict__ R1e, const float* __restrict__ b1e,
    int n) {
    __shared__ float ysh[FOU1];
    __shared__ float red[8];
    for (int t = threadIdx.x; t < FOU1; t += blockDim.x) ysh[t] = 0.f;
    __syncthreads();

    int lane = threadIdx.x & 31;
    int wid  = threadIdx.x >> 5;
    int warpsTotal = gridDim.x * 8;
    int gw = blockIdx.x * 8 + wid;

    float yloc[4] = {0.f, 0.f, 0.f, 0.f};
    float dacc = 0.f;

    for (int i = gw; i < n; i += warpsTotal) {
        float xv = 0.f, av = 0.f;
        if (lane < 5) { xv = x[i * 5 + lane]; }
        if (lane < 6) { av = d_agg[(size_t)i * 8 + lane]; }
        float cv   = __shfl_sync(0xffffffffu, av, 5);
        float degv = d_deg[i];
        float denom = fmaxf(cv, 1.0f);
        float xa[5], aa[5];
#pragma unroll
        for (int k = 0; k < 5; k++) {
            xa[k] = __shfl_sync(0xffffffffu, xv, k);
            aa[k] = __shfl_sync(0xffffffffu, av, k) / denom;
        }
        float sv[8];
#pragma unroll
        for (int j = 0; j < 8; j++) {
            int c = j * 32 + lane;
            float acc = b1p[c];
#pragma unroll
            for (int k = 0; k < 5; k++) {
                acc = fmaf(aa[k], W1p[k * 256 + c], acc);
                acc = fmaf(xa[k], R1p[k * 256 + c], acc);
            }
            sv[j] = acc;
        }
        float m = sv[0];
#pragma unroll
        for (int j = 1; j < 8; j++) m = fmaxf(m, sv[j]);
#pragma unroll
        for (int o = 16; o > 0; o >>= 1) m = fmaxf(m, __shfl_xor_sync(0xffffffffu, m, o));
        float sum = 0.f;
#pragma unroll
        for (int j = 0; j < 8; j++) { sv[j] = __expf(sv[j] - m); sum += sv[j]; }
#pragma unroll
        for (int o = 16; o > 0; o >>= 1) sum += __shfl_xor_sync(0xffffffffu, sum, o);
        float inv = 1.0f / sum;
        float sq = 0.f;
        float maxr = 0.f;
#pragma unroll
        for (int j = 0; j < 8; j++) {
            float p = sv[j] * inv;
            sv[j] = p;
            d_S16[(size_t)i * 256 + j * 32 + lane] = __float2half_rn(p);
            maxr = fmaxf(maxr, fabsf(p - 0.00390625f));
            sq = fmaf(p, p, sq);
        }
#pragma unroll
        for (int o = 16; o > 0; o >>= 1) maxr = fmaxf(maxr, __shfl_xor_sync(0xffffffffu, maxr, o));
        float srow   = (maxr > 0.f) ? 127.0f / maxr : 0.f;
        float invrow = maxr * (1.0f / 127.0f);
#pragma unroll
        for (int j = 0; j < 8; j++) {
            int q = __float2int_rn((sv[j] - 0.00390625f) * srow);
            d_Q8[(size_t)i * 256 + j * 32 + lane] = (char)q;
        }
        if (lane == 0) {
            float isq = (degv > 0.f) ? rsqrtf(degv) : 0.f;
            d_aux[i] = make_float2(isq, invrow);
        }
        if (degv > 0.f) dacc += sq;
#pragma unroll
        for (int j = 0; j < 4; j++) {
            int c = j * 32 + lane;
            float acc = b1e[c];
#pragma unroll
            for (int k = 0; k < 5; k++) {
                acc = fmaf(aa[k], W1e[k * 128 + c], acc);
                acc = fmaf(xa[k], R1e[k * 128 + c], acc);
            }
            acc = fmaxf(acc, 0.f);
            d_Y16[(size_t)i * 128 + c] = __float2half_rn(acc);
            yloc[j] += acc;
        }
    }
#pragma unroll
    for (int o = 16; o > 0; o >>= 1) dacc += __shfl_xor_sync(0xffffffffu, dacc, o);
    if (lane == 0) red[wid] = dacc;
#pragma unroll
    for (int j = 0; j < 4; j++) atomicAdd(&ysh[j * 32 + lane], yloc[j]);
    __syncthreads();
    if (threadIdx.x == 0) {
        float t = 0.f;
        for (int k = 0; k < 8; k++) t += red[k];
        atomicAdd(&d_scal[0], t);
    }
    if (threadIdx.x < FOU1) atomicAdd(&d_ysum[threadIdx.x], ysh[threadIdx.x]);
}

// ---------------- K3: pooled += S^T Y, 128c x 64f tiles, 3 CTA/SM, cp.async ----------------
#define CHUNK 32
#define APITCH 136
#define BPITCH 72

__device__ __forceinline__ unsigned shaddr(const void* p) {
    return (unsigned)__cvta_generic_to_shared(p);
}
__device__ __forceinline__ void ldsm4t(unsigned* r, unsigned addr) {
    asm volatile("ldmatrix.sync.aligned.m8n8.x4.trans.shared.b16 {%0,%1,%2,%3}, [%4];"
                 : "=r"(r[0]), "=r"(r[1]), "=r"(r[2]), "=r"(r[3]) : "r"(addr));
}
__device__ __forceinline__ void mma16816(float* c, const unsigned* a, const unsigned* b) {
    asm volatile("mma.sync.aligned.m16n8k16.row.col.f32.f16.f16.f32 "
                 "{%0,%1,%2,%3}, {%4,%5,%6,%7}, {%8,%9}, {%0,%1,%2,%3};"
                 : "+f"(c[0]), "+f"(c[1]), "+f"(c[2]), "+f"(c[3])
                 : "r"(a[0]), "r"(a[1]), "r"(a[2]), "r"(a[3]), "r"(b[0]), "r"(b[1]));
}
__device__ __forceinline__ void cpasync4(unsigned saddr, const void* g, int sz) {
    asm volatile("cp.async.ca.shared.global [%0], [%1], 4, %2;"
                 :: "r"(saddr), "l"(g), "r"(sz) : "memory");
}

__global__ __launch_bounds__(256, 3) void k3_pool(int n) {
    __shared__ __align__(16) __half A_s[2][CHUNK][APITCH];   // S chunk, 128 chalf cols
    __shared__ __align__(16) __half B_s[2][CHUNK][BPITCH];   // Y chunk, 64 fhalf cols
    int b     = blockIdx.x;
    int chalf = b & 1;
    int fhalf = (b >> 1) & 1;
    int kb    = b >> 2;
    int per   = (n + KSPLIT3 - 1) / KSPLIT3;
    int lo    = kb * per;
    int hi    = min(n, lo + per);

    int tid  = threadIdx.x;
    int lane = tid & 31;
    int wid  = tid >> 5;
    int m_base  = (wid >> 1) * 32;    // 4 m-tiles of 32 within 128
    int f_basew = (wid & 1) * 32;     // 2 f-tiles of 32 within 64

    float acc[2][4][4];
#pragma unroll
    for (int p = 0; p < 2; p++)
#pragma unroll
        for (int q = 0; q < 4; q++)
#pragma unroll
            for (int v = 0; v < 4; v++) acc[p][q][v] = 0.f;

    auto issue = [&](int i0, int bf) {
        // A: 32 rows x 64 half2
#pragma unroll
        for (int rep = 0; rep < 8; rep++) {
            int e2    = rep * 256 + tid;
            int i_loc = e2 >> 6;
            int c2    = e2 & 63;
            int g     = i0 + i_loc;
            int gc    = min(g, n - 1);
            int sz    = (g < hi) ? 4 : 0;
            cpasync4(shaddr(&A_s[bf][i_loc][2 * c2]),
                     &d_S16[(size_t)gc * 256 + chalf * 128 + 2 * c2], sz);
        }
        // B: 32 rows x 32 half2
#pragma unroll
        for (int rep = 0; rep < 4; rep++) {
            int e2    = rep * 256 + tid;
            int i_loc = e2 >> 5;
            int c2    = e2 & 31;
            int g     = i0 + i_loc;
            int gc    = min(g, n - 1);
            int sz    = (g < hi) ? 4 : 0;
            cpasync4(shaddr(&B_s[bf][i_loc][2 * c2]),
                     &d_Y16[(size_t)gc * 128 + fhalf * 64 + 2 * c2], sz);
        }
    };

    int buf = 0;
    if (lo < hi) {
        issue(lo, 0);
        asm volatile("cp.async.commit_group;" ::: "memory");
    }
    for (int i0 = lo; i0 < hi; i0 += CHUNK) {
        int nxt = i0 + CHUNK;
        if (nxt < hi) {
            issue(nxt, buf ^ 1);
            asm volatile("cp.async.commit_group;" ::: "memory");
            asm volatile("cp.async.wait_group 1;" ::: "memory");
        } else {
            asm volatile("cp.async.wait_group 0;" ::: "memory");
        }
        __syncthreads();
#pragma unroll
        for (int t = 0; t < 2; t++) {
            int krA = t * 16 + (lane & 7) + ((lane >> 4) << 3);
            unsigned aaddr = shaddr(&A_s[buf][krA][m_base + ((lane >> 3) & 1) * 8]);
            unsigned afrag[2][4];
            ldsm4t(afrag[0], aaddr);
            ldsm4t(afrag[1], aaddr + 32);
            int krB = t * 16 + (lane & 7) + (lane & 8);
            unsigned baddr = shaddr(&B_s[buf][krB][f_basew + ((lane >> 4) & 1) * 8]);
            unsigned bfrag[2][4];
#pragma unroll
            for (int gq = 0; gq < 2; gq++)
                ldsm4t(bfrag[gq], baddr + gq * 32);
#pragma unroll
            for (int p = 0; p < 2; p++)
#pragma unroll
                for (int q = 0; q < 4; q++)
                    mma16816(acc[p][q], afrag[p], &bfrag[q >> 1][(q & 1) * 2]);
        }
        __syncthreads();
        buf ^= 1;
    }

    int r    = lane >> 2;
    int col2 = (lane & 3) * 2;
#pragma unroll
    for (int p = 0; p < 2; p++) {
#pragma unroll
        for (int q = 0; q < 4; q++) {
            int cg = chalf * 128 + m_base + p * 16 + r;
            int f  = fhalf * 64 + f_basew + q * 8 + col2;
            float* p0 = &d_pooled[(size_t)cg * FOU1 + f];
            float* p1 = &d_pooled[(size_t)(cg + 8) * FOU1 + f];
            asm volatile("red.global.add.v2.f32 [%0], {%1,%2};"
                         :: "l"(p0), "f"(acc[p][q][0]), "f"(acc[p][q][1]) : "memory");
            asm volatile("red.global.add.v2.f32 [%0], {%1,%2};"
                         :: "l"(p1), "f"(acc[p][q][2]), "f"(acc[p][q][3]) : "memory");
        }
    }
}

// ---------------- K5: edge SDDMM, 4 edges/warp (8 lanes each), coalesced int8 DP4A ----------------
__global__ __launch_bounds__(256) void k5_edge(const int* __restrict__ ei,
                                               const float* __restrict__ w, int e) {
    __shared__ float redr[8];
    __shared__ float redc[8];
    int lane = threadIdx.x & 31;
    int sub  = lane & 7;      // 8 lanes per edge; lane covers bytes [16*sub,16*sub+16) and +128
    int quar = lane >> 3;     // which of 4 edges in this warp
    int wid  = threadIdx.x >> 5;
    int gw = blockIdx.x * 8 + wid;
    int tw = gridDim.x * 8;
    float accr = 0.f;   // sum c_e * <r_i, r_j>  (scales folded in)
    float accc = 0.f;   // 8 * sum c_e
#pragma unroll 2
    for (int j = 4 * gw + quar; j < e; j += 4 * tw) {
        int s = ei[j];
        int d = ei[e + j];
        float wv = w[j];
        float2 as = d_aux[s];
        float2 ad = d_aux[d];
        float csc = wv * as.x * ad.x;
        float scl = csc * as.y * ad.y;
        const int4* ps = (const int4*)&d_Q8[(size_t)s * 256];
        const int4* pd = (const int4*)&d_Q8[(size_t)d * 256];
        int4 a0 = ps[sub];        // lanes 0..7 cover [0,128) contiguously
        int4 a1 = ps[sub + 8];    // lanes 0..7 cover [128,256) contiguously
        int4 b0 = pd[sub];
        int4 b1 = pd[sub + 8];
        int id = __dp4a(a0.x, b0.x, __dp4a(a0.y, b0.y,
                 __dp4a(a0.z, b0.z, __dp4a(a0.w, b0.w, 0))));
        id     = __dp4a(a1.x, b1.x, __dp4a(a1.y, b1.y,
                 __dp4a(a1.z, b1.z, __dp4a(a1.w, b1.w, id))));
        accr = fmaf(scl, (float)id, accr);
        accc += csc;
    }
#pragma unroll
    for (int o = 16; o > 0; o >>= 1) {
        accr += __shfl_xor_sync(0xffffffffu, accr, o);
        accc += __shfl_xor_sync(0xffffffffu, accc, o);
    }
    if (lane == 0) { redr[wid] = accr; redc[wid] = accc * (1.0f / 8.0f); }
    __syncthreads();
    if (threadIdx.x == 0) {
        float tr = 0.f, tc = 0.f;
        for (int k = 0; k < 8; k++) { tr += redr[k]; tc += redc[k]; }
        atomicAdd(&d_scal[1], tr);
        atomicAdd(&d_scal[2], tc);
    }
}

// ---------------- K6: g[k] += relu(mw[k] + pooled[c] . R2e[:,k]) ----------------
__global__ __launch_bounds__(256) void k6_y2(const float* __restrict__ R2e,
                                             const float* __restrict__ W2e,
                                             const float* __restrict__ b2e) {
    __shared__ float prow[FOU1];
    __shared__ float ys[FOU1];
    int c = blockIdx.x;
    if (threadIdx.x < FOU1) {
        prow[threadIdx.x] = d_pooled[c * FOU1 + threadIdx.x];
        ys[threadIdx.x]   = d_ysum[threadIdx.x] * (1.0f / 256.0f);
    }
    __syncthreads();
    int k = threadIdx.x;
    float acc = b2e[k];
#pragma unroll 4
    for (int f = 0; f < FOU1; f++) {
        acc = fmaf(ys[f],   W2e[f * 256 + k], acc);
        acc = fmaf(prow[f], R2e[f * 256 + k], acc);
    }
    acc = fmaxf(acc, 0.f);
    atomicAdd(&d_g[k], acc);
}

// ---------------- K7: MLP head + log_softmax + reg1 ----------------
__global__ __launch_bounds__(256) void k7_final(
    const float* __restrict__ Wl1, const float* __restrict__ bl1,
    const float* __restrict__ Wl2, const float* __restrict__ bl2,
    float* __restrict__ out, int n, int out_size) {
    __shared__ float gsh[FOU2];
    __shared__ float h1[HLIN];
    __shared__ float lg[OUTP];
    int t = threadIdx.x;
    gsh[t] = d_g[t];
    __syncthreads();
    float acc = bl1[t];
    for (int k = 0; k < FOU2; k++) acc = fmaf(gsh[k], Wl1[k * HLIN + t], acc);
    h1[t] = fmaxf(acc, 0.f);
    __syncthreads();
    if (t < OUTP) {
        float a2 = bl2[t];
        for (int j = 0; j < HLIN; j++) a2 = fmaf(h1[j], Wl2[j * OUTP + t], a2);
        lg[t] = a2;
    }
    __syncthreads();
    if (t == 0) {
        float m = lg[0];
        for (int o = 1; o < OUTP; o++) m = fmaxf(m, lg[o]);
        float s = 0.f;
        for (int o = 0; o < OUTP; o++) s += expf(lg[o] - m);
        float lse = m + logf(s);
        for (int o = 0; o < OUTP; o++) out[o] = lg[o] - lse;
        if (out_size > OUTP) {
            float edge = d_scal[2] * 0.00390625f + d_scal[1];
            out[OUTP] = (d_scal[0] - edge) / (float)n;
        }
    }
}

// ---------------- launch ----------------
extern "C" void kernel_launch(void* const* d_in, const int* in_sizes, int n_in,
                              void* d_out, int out_size) {
    const float* x   = (const float*)d_in[0];
    const int*   ei  = (const int*)d_in[1];
    const float* wht = (const float*)d_in[2];
    const float* W1p = (const float*)d_in[3];
    const float* R1p = (const float*)d_in[4];
    const float* b1p = (const float*)d_in[5];
    const float* W1e = (const float*)d_in[6];
    const float* R1e = (const float*)d_in[7];
    const float* b1e = (const float*)d_in[8];
    // d_in[9..11] = W2p, R2p, b2p: dead (softmax over size-1 axis == 1)
    const float* W2e = (const float*)d_in[12];
    const float* R2e = (const float*)d_in[13];
    const float* b2e = (const float*)d_in[14];
    const float* Wl1 = (const float*)d_in[15];
    const float* bl1 = (const float*)d_in[16];
    const float* Wl2 = (const float*)d_in[17];
    const float* bl2 = (const float*)d_in[18];

    int n = in_sizes[0] / 5;
    int e = in_sizes[2];

    k0_zero<<<512, 256>>>(x, n);
    k1_edge_agg<<<(e + 255) / 256, 256>>>(ei, wht, n, e);
    k2_node<<<592, 256>>>(x, W1p, R1p, b1p, W1e, R1e, b1e, n);
    k5_edge<<<1184, 256>>>(ei, wht, e);      // slot 4: ncu profiles this launch
    k3_pool<<<4 * KSPLIT3, 256>>>(n);
    k6_y2<<<CLUS, 256>>>(R2e, W2e, b2e);
    k7_final<<<1, 256>>>(Wl1, bl1, Wl2, bl2, (float*)d_out, n, out_size);
}